// round 8
// baseline (speedup 1.0000x reference)
#include <cuda_runtime.h>
#include <cuda_fp16.h>
#include <cstdint>

// Problem constants
#define M_DIM 8192
#define K_DIM 4096
#define N_DIM 14336
#define GSZ   128

// GEMM tiling
#define MT 128
#define NT 128
#define KC 64                       // K per pipeline chunk
#define CHUNKS (K_DIM / KC)         // 64
#define STAGES 4
#define MTILES (M_DIM / MT)         // 64
#define NTILES (N_DIM / NT)         // 112
#define THREADS 256

#define A_STAGE (MT * KC * 2)       // 16 KB
#define B_STAGE (NT * KC * 2)       // 16 KB
#define STAGE_BYTES (A_STAGE + B_STAGE)
#define SMEM_TOTAL (STAGES * STAGE_BYTES)   // 128 KB

// Fused prepass geometry
#define XV4     ((size_t)M_DIM * K_DIM / 4)   // float4 items
#define XBLOCKS ((int)(XV4 / 256))            // 32768
#define WWORDS  ((size_t)N_DIM * K_DIM / 8)   // packed int32 items
#define WBLOCKS ((int)(WWORDS / 256))         // 28672

// Pre-converted operands (device-global scratch; allocation-free)
__device__ __half g_xh[(size_t)M_DIM * K_DIM];   // 64 MB: x as fp16
__device__ __half g_wh[(size_t)N_DIM * K_DIM];   // 112 MB: dequantized W as fp16

__device__ __forceinline__ uint32_t s2u(const void* p) {
    uint32_t a;
    asm("{ .reg .u64 t; cvta.to.shared.u64 t, %1; cvt.u32.u64 %0, t; }" : "=r"(a) : "l"(p));
    return a;
}

__device__ __forceinline__ void cpa16(uint32_t dst, const void* src) {
    asm volatile("cp.async.cg.shared.global [%0], [%1], 16;" :: "r"(dst), "l"(src) : "memory");
}

// ---------------- Fused prepass: x fp32->fp16 AND int4 W -> fp16 ----------------
__global__ void prep_kernel(const float* __restrict__ x,
                            const int* __restrict__ w4,
                            const float* __restrict__ wsc) {
    if (blockIdx.x < XBLOCKS) {
        size_t i = (size_t)blockIdx.x * 256 + threadIdx.x;   // one float4
        float4 v = reinterpret_cast<const float4*>(x)[i];
        __half2 h0 = __floats2half2_rn(v.x, v.y);
        __half2 h1 = __floats2half2_rn(v.z, v.w);
        uint2 u;
        u.x = *reinterpret_cast<uint32_t*>(&h0);
        u.y = *reinterpret_cast<uint32_t*>(&h1);
        reinterpret_cast<uint2*>(g_xh)[i] = u;
    } else {
        size_t i = (size_t)(blockIdx.x - XBLOCKS) * 256 + threadIdx.x;  // one packed word
        int n  = (int)(i >> 9);           // K/8 = 512 words per row
        int kw = (int)(i & 511);
        uint32_t w = (uint32_t)w4[i];
        float s = __ldg(wsc + (size_t)n * (K_DIM / GSZ) + (kw >> 4));
        __half2 h[4];
#pragma unroll
        for (int p = 0; p < 4; p++) {
            int v0 = ((int)(w << (28 - 8 * p))) >> 28;        // nibble 2p
            int v1 = ((int)(w << (24 - 8 * p))) >> 28;        // nibble 2p+1
            h[p] = __floats2half2_rn((float)v0 * s, (float)v1 * s);
        }
        uint4 u;
        u.x = *reinterpret_cast<uint32_t*>(&h[0]);
        u.y = *reinterpret_cast<uint32_t*>(&h[1]);
        u.z = *reinterpret_cast<uint32_t*>(&h[2]);
        u.w = *reinterpret_cast<uint32_t*>(&h[3]);
        reinterpret_cast<uint4*>(g_wh)[i] = u;
    }
}

// ---------------- GEMM mainloop helpers ----------------
__device__ __forceinline__ void load_stage(uint32_t sstage, const __half* __restrict__ Ag,
                                           const __half* __restrict__ Bg, int k0, int tid) {
    // A: 128 rows x 8 chunks of 16B, XOR-swizzled within the 128B row
#pragma unroll
    for (int i = 0; i < 4; i++) {
        int ch = tid + i * 256;
        int r = ch >> 3, cc = ch & 7;
        cpa16(sstage + (uint32_t)((r << 7) + ((cc ^ (r & 7)) << 4)),
              Ag + (size_t)r * K_DIM + k0 + cc * 8);
    }
#pragma unroll
    for (int i = 0; i < 4; i++) {
        int ch = tid + i * 256;
        int r = ch >> 3, cc = ch & 7;
        cpa16(sstage + A_STAGE + (uint32_t)((r << 7) + ((cc ^ (r & 7)) << 4)),
              Bg + (size_t)r * K_DIM + k0 + cc * 8);
    }
}

#define LDSM4(r0, r1, r2, r3, addr)                                         \
    asm volatile("ldmatrix.sync.aligned.m8n8.x4.shared.b16 {%0,%1,%2,%3}, [%4];" \
                 : "=r"(r0), "=r"(r1), "=r"(r2), "=r"(r3) : "r"(addr))

// fp16-accumulate MMA: d = 2x b32 regs holding 4 halves {c0,c1,c2,c3}
#define MMA16816_H(d, a, b)                                                 \
    asm volatile("mma.sync.aligned.m16n8k16.row.col.f16.f16.f16.f16 "       \
                 "{%0,%1}, {%2,%3,%4,%5}, {%6,%7}, {%0,%1};"                \
                 : "+r"(d[0]), "+r"(d[1])                                   \
                 : "r"(a[0]), "r"(a[1]), "r"(a[2]), "r"(a[3]),              \
                   "r"(b[0]), "r"(b[1]))

__global__ void __launch_bounds__(THREADS, 1)
gemm_kernel(const float* __restrict__ xscale, const float* __restrict__ gate,
            const float* __restrict__ bias, float* __restrict__ out)
{
    extern __shared__ char smem[];
    const uint32_t sbase = s2u(smem);
    const int tid = threadIdx.x;

    // Band rasterization: 8 M-tiles per panel for L2 reuse within a wave
    int pid = blockIdx.x;
    int panel = pid / (8 * NTILES);
    int rem = pid - panel * 8 * NTILES;
    int nt = rem >> 3;
    int mt = (panel << 3) + (rem & 7);
    const int m0 = mt * MT, n0 = nt * NT;

    const __half* Ag = g_xh + (size_t)m0 * K_DIM;
    const __half* Bg = g_wh + (size_t)n0 * K_DIM;

    // Prologue: fill STAGES-1 pipeline stages
#pragma unroll
    for (int c = 0; c < STAGES - 1; c++) {
        load_stage(sbase + (uint32_t)c * STAGE_BYTES, Ag, Bg, c * KC, tid);
        asm volatile("cp.async.commit_group;" ::: "memory");
    }

    const int lane = tid & 31, warp = tid >> 5;
    const int wm = warp & 1, wn = warp >> 1;          // warp grid 2(M) x 4(N)
    const int rl = ((lane >> 3) & 1) * 8 + (lane & 7); // ldmatrix row-within-16
    const int cl = lane >> 4;                          // ldmatrix chunk select
    const int sw = lane & 7;                           // swizzle xor
    const uint32_t aoff = (uint32_t)((wm * 64 + rl) << 7);
    const uint32_t boff = (uint32_t)(A_STAGE + ((wn * 32 + rl) << 7));

    float acc[4][4][4];
#pragma unroll
    for (int mi = 0; mi < 4; mi++)
#pragma unroll
        for (int ni = 0; ni < 4; ni++)
#pragma unroll
            for (int j = 0; j < 4; j++) acc[mi][ni][j] = 0.0f;

#pragma unroll 1
    for (int c = 0; c < CHUNKS; c++) {
        asm volatile("cp.async.wait_group %0;" :: "n"(STAGES - 2) : "memory");
        __syncthreads();
        const int cn = c + STAGES - 1;
        if (cn < CHUNKS)
            load_stage(sbase + (uint32_t)(cn % STAGES) * STAGE_BYTES, Ag, Bg, cn * KC, tid);
        asm volatile("cp.async.commit_group;" ::: "memory");

        const uint32_t sa = sbase + (uint32_t)(c % STAGES) * STAGE_BYTES;

        // fp16 chunk accumulators (zeroed per chunk, promoted to fp32 after)
        uint32_t hacc[4][4][2];
#pragma unroll
        for (int mi = 0; mi < 4; mi++)
#pragma unroll
            for (int ni = 0; ni < 4; ni++) {
                hacc[mi][ni][0] = 0u;
                hacc[mi][ni][1] = 0u;
            }

#pragma unroll
        for (int ks = 0; ks < 4; ks++) {
            const uint32_t coff = (uint32_t)((((ks << 1) + cl) ^ sw) << 4);
            uint32_t af[4][4], bf[4][2];
#pragma unroll
            for (int mi = 0; mi < 4; mi++)
                LDSM4(af[mi][0], af[mi][1], af[mi][2], af[mi][3],
                      sa + aoff + (uint32_t)(mi * 2048) + coff);
#pragma unroll
            for (int p = 0; p < 2; p++) {
                uint32_t r0, r1, r2, r3;
                LDSM4(r0, r1, r2, r3, sa + boff + (uint32_t)(p * 2048) + coff);
                bf[2 * p][0] = r0; bf[2 * p][1] = r2;
                bf[2 * p + 1][0] = r1; bf[2 * p + 1][1] = r3;
            }
#pragma unroll
            for (int mi = 0; mi < 4; mi++)
#pragma unroll
                for (int ni = 0; ni < 4; ni++)
                    MMA16816_H(hacc[mi][ni], af[mi], bf[ni]);
        }

        // Promote chunk sums to fp32 accumulators
#pragma unroll
        for (int mi = 0; mi < 4; mi++)
#pragma unroll
            for (int ni = 0; ni < 4; ni++) {
                float2 lo = __half22float2(*reinterpret_cast<__half2*>(&hacc[mi][ni][0]));
                float2 hi = __half22float2(*reinterpret_cast<__half2*>(&hacc[mi][ni][1]));
                acc[mi][ni][0] += lo.x;
                acc[mi][ni][1] += lo.y;
                acc[mi][ni][2] += hi.x;
                acc[mi][ni][3] += hi.y;
            }
    }

    // Epilogue: y = (acc * x_scale + bias) * gate, straight from registers
#pragma unroll
    for (int mi = 0; mi < 4; mi++) {
        const int r = m0 + wm * 64 + mi * 16 + (lane >> 2);
        const float xs0 = __ldg(xscale + r);
        const float xs1 = __ldg(xscale + r + 8);
        const float* g0 = gate + (size_t)r * N_DIM;
        const float* g1 = g0 + (size_t)8 * N_DIM;
        float* o0 = out + (size_t)r * N_DIM;
        float* o1 = o0 + (size_t)8 * N_DIM;
#pragma unroll
        for (int ni = 0; ni < 4; ni++) {
            const int cc = n0 + wn * 32 + ni * 8 + (lane & 3) * 2;
            float2 bb = *reinterpret_cast<const float2*>(bias + cc);
            float2 ga = *reinterpret_cast<const float2*>(g0 + cc);
            float2 gb = *reinterpret_cast<const float2*>(g1 + cc);
            float2 v0, v1;
            v0.x = (acc[mi][ni][0] * xs0 + bb.x) * ga.x;
            v0.y = (acc[mi][ni][1] * xs0 + bb.y) * ga.y;
            v1.x = (acc[mi][ni][2] * xs1 + bb.x) * gb.x;
            v1.y = (acc[mi][ni][3] * xs1 + bb.y) * gb.y;
            *reinterpret_cast<float2*>(o0 + cc) = v0;
            *reinterpret_cast<float2*>(o1 + cc) = v1;
        }
    }
}

extern "C" void kernel_launch(void* const* d_in, const int* in_sizes, int n_in,
                              void* d_out, int out_size) {
    (void)in_sizes; (void)n_in; (void)out_size;
    const float* x      = (const float*)d_in[0];
    const float* xscale = (const float*)d_in[1];
    const int*   w4     = (const int*)d_in[2];
    const float* wsc    = (const float*)d_in[3];
    const float* gate   = (const float*)d_in[4];
    const float* bias   = (const float*)d_in[5];
    float* out = (float*)d_out;

    prep_kernel<<<XBLOCKS + WBLOCKS, 256>>>(x, w4, wsc);

    cudaFuncSetAttribute(gemm_kernel,
                         cudaFuncAttributeMaxDynamicSharedMemorySize, SMEM_TOTAL);
    gemm_kernel<<<MTILES * NTILES, THREADS, SMEM_TOTAL>>>(xscale, gate, bias, out);
}

// round 9
// speedup vs baseline: 1.1046x; 1.1046x over previous
#include <cuda_runtime.h>
#include <cuda_fp16.h>
#include <cstdint>

// Problem constants
#define M_DIM 8192
#define K_DIM 4096
#define N_DIM 14336
#define GSZ   128

// GEMM tiling
#define MT 128
#define NT 128
#define KC 64                       // K per pipeline chunk
#define CHUNKS (K_DIM / KC)         // 64
#define STAGES 4
#define MTILES (M_DIM / MT)         // 64
#define NTILES (N_DIM / NT)         // 112
#define THREADS 512

#define A_STAGE (MT * KC * 2)       // 16 KB
#define B_STAGE (NT * KC * 2)       // 16 KB
#define STAGE_BYTES (A_STAGE + B_STAGE)
#define SMEM_TOTAL (STAGES * STAGE_BYTES)   // 128 KB

// Fused prepass geometry
#define XV4     ((size_t)M_DIM * K_DIM / 4)   // float4 items
#define XBLOCKS ((int)(XV4 / 256))            // 32768
#define WWORDS  ((size_t)N_DIM * K_DIM / 8)   // packed int32 items
#define WBLOCKS ((int)(WWORDS / 256))         // 28672

// Pre-converted operands (device-global scratch; allocation-free)
__device__ __half g_xh[(size_t)M_DIM * K_DIM];   // 64 MB: x as fp16
__device__ __half g_wh[(size_t)N_DIM * K_DIM];   // 112 MB: dequantized W as fp16

__device__ __forceinline__ uint32_t s2u(const void* p) {
    uint32_t a;
    asm("{ .reg .u64 t; cvta.to.shared.u64 t, %1; cvt.u32.u64 %0, t; }" : "=r"(a) : "l"(p));
    return a;
}

__device__ __forceinline__ void cpa16(uint32_t dst, const void* src) {
    asm volatile("cp.async.cg.shared.global [%0], [%1], 16;" :: "r"(dst), "l"(src) : "memory");
}

// ---------------- Fused prepass: x fp32->fp16 AND int4 W -> fp16 ----------------
__global__ void prep_kernel(const float* __restrict__ x,
                            const int* __restrict__ w4,
                            const float* __restrict__ wsc) {
    if (blockIdx.x < XBLOCKS) {
        size_t i = (size_t)blockIdx.x * 256 + threadIdx.x;   // one float4
        float4 v = reinterpret_cast<const float4*>(x)[i];
        __half2 h0 = __floats2half2_rn(v.x, v.y);
        __half2 h1 = __floats2half2_rn(v.z, v.w);
        uint2 u;
        u.x = *reinterpret_cast<uint32_t*>(&h0);
        u.y = *reinterpret_cast<uint32_t*>(&h1);
        reinterpret_cast<uint2*>(g_xh)[i] = u;
    } else {
        size_t i = (size_t)(blockIdx.x - XBLOCKS) * 256 + threadIdx.x;  // one packed word
        int n  = (int)(i >> 9);           // K/8 = 512 words per row
        int kw = (int)(i & 511);
        uint32_t w = (uint32_t)w4[i];
        float s = __ldg(wsc + (size_t)n * (K_DIM / GSZ) + (kw >> 4));
        __half2 h[4];
#pragma unroll
        for (int p = 0; p < 4; p++) {
            int v0 = ((int)(w << (28 - 8 * p))) >> 28;        // nibble 2p
            int v1 = ((int)(w << (24 - 8 * p))) >> 28;        // nibble 2p+1
            h[p] = __floats2half2_rn((float)v0 * s, (float)v1 * s);
        }
        uint4 u;
        u.x = *reinterpret_cast<uint32_t*>(&h[0]);
        u.y = *reinterpret_cast<uint32_t*>(&h[1]);
        u.z = *reinterpret_cast<uint32_t*>(&h[2]);
        u.w = *reinterpret_cast<uint32_t*>(&h[3]);
        reinterpret_cast<uint4*>(g_wh)[i] = u;
    }
}

// ---------------- GEMM mainloop helpers ----------------
__device__ __forceinline__ void load_stage(uint32_t sstage, const __half* __restrict__ Ag,
                                           const __half* __restrict__ Bg, int k0, int tid) {
    // A: 128 rows x 8 chunks of 16B, XOR-swizzled within the 128B row
#pragma unroll
    for (int i = 0; i < 2; i++) {
        int ch = tid + i * 512;
        int r = ch >> 3, cc = ch & 7;
        cpa16(sstage + (uint32_t)((r << 7) + ((cc ^ (r & 7)) << 4)),
              Ag + (size_t)r * K_DIM + k0 + cc * 8);
    }
#pragma unroll
    for (int i = 0; i < 2; i++) {
        int ch = tid + i * 512;
        int r = ch >> 3, cc = ch & 7;
        cpa16(sstage + A_STAGE + (uint32_t)((r << 7) + ((cc ^ (r & 7)) << 4)),
              Bg + (size_t)r * K_DIM + k0 + cc * 8);
    }
}

#define LDSM4(r0, r1, r2, r3, addr)                                         \
    asm volatile("ldmatrix.sync.aligned.m8n8.x4.shared.b16 {%0,%1,%2,%3}, [%4];" \
                 : "=r"(r0), "=r"(r1), "=r"(r2), "=r"(r3) : "r"(addr))

#define MMA16816(d, a, b)                                                   \
    asm volatile("mma.sync.aligned.m16n8k16.row.col.f32.f16.f16.f32 "       \
                 "{%0,%1,%2,%3}, {%4,%5,%6,%7}, {%8,%9}, {%0,%1,%2,%3};"    \
                 : "+f"(d[0]), "+f"(d[1]), "+f"(d[2]), "+f"(d[3])           \
                 : "r"(a[0]), "r"(a[1]), "r"(a[2]), "r"(a[3]),              \
                   "r"(b[0]), "r"(b[1]))

__global__ void __launch_bounds__(THREADS, 1)
gemm_kernel(const float* __restrict__ xscale, const float* __restrict__ gate,
            const float* __restrict__ bias, float* __restrict__ out)
{
    extern __shared__ char smem[];
    const uint32_t sbase = s2u(smem);
    const int tid = threadIdx.x;

    // Band rasterization: 8 M-tiles per panel for L2 reuse within a wave
    int pid = blockIdx.x;
    int panel = pid / (8 * NTILES);
    int rem = pid - panel * 8 * NTILES;
    int nt = rem >> 3;
    int mt = (panel << 3) + (rem & 7);
    const int m0 = mt * MT, n0 = nt * NT;

    const __half* Ag = g_xh + (size_t)m0 * K_DIM;
    const __half* Bg = g_wh + (size_t)n0 * K_DIM;

    // Prologue: fill STAGES-1 pipeline stages
#pragma unroll
    for (int c = 0; c < STAGES - 1; c++) {
        load_stage(sbase + (uint32_t)c * STAGE_BYTES, Ag, Bg, c * KC, tid);
        asm volatile("cp.async.commit_group;" ::: "memory");
    }

    const int lane = tid & 31, warp = tid >> 5;
    const int wm = warp & 3, wn = warp >> 2;           // warp grid 4(M) x 4(N)
    const int rl = lane & 15;                          // ldmatrix row-within-16
    const int cl = lane >> 4;                          // ldmatrix chunk select
    const int sw = lane & 7;                           // swizzle xor
    const uint32_t aoff = (uint32_t)((wm * 32 + rl) << 7);
    const uint32_t boff = (uint32_t)(A_STAGE + ((wn * 32 + rl) << 7));

    float acc[2][4][4];
#pragma unroll
    for (int mi = 0; mi < 2; mi++)
#pragma unroll
        for (int ni = 0; ni < 4; ni++)
#pragma unroll
            for (int j = 0; j < 4; j++) acc[mi][ni][j] = 0.0f;

#pragma unroll 1
    for (int c = 0; c < CHUNKS; c++) {
        asm volatile("cp.async.wait_group %0;" :: "n"(STAGES - 2) : "memory");
        __syncthreads();
        const int cn = c + STAGES - 1;
        if (cn < CHUNKS)
            load_stage(sbase + (uint32_t)(cn % STAGES) * STAGE_BYTES, Ag, Bg, cn * KC, tid);
        asm volatile("cp.async.commit_group;" ::: "memory");

        const uint32_t sa = sbase + (uint32_t)(c % STAGES) * STAGE_BYTES;
#pragma unroll
        for (int ks = 0; ks < 4; ks++) {
            const uint32_t coff = (uint32_t)((((ks << 1) + cl) ^ sw) << 4);
            uint32_t af[2][4], bf[4][2];
#pragma unroll
            for (int mi = 0; mi < 2; mi++)
                LDSM4(af[mi][0], af[mi][1], af[mi][2], af[mi][3],
                      sa + aoff + (uint32_t)(mi * 2048) + coff);
#pragma unroll
            for (int p = 0; p < 2; p++) {
                uint32_t r0, r1, r2, r3;
                LDSM4(r0, r1, r2, r3, sa + boff + (uint32_t)(p * 2048) + coff);
                bf[2 * p][0] = r0; bf[2 * p][1] = r2;
                bf[2 * p + 1][0] = r1; bf[2 * p + 1][1] = r3;
            }
#pragma unroll
            for (int mi = 0; mi < 2; mi++)
#pragma unroll
                for (int ni = 0; ni < 4; ni++)
                    MMA16816(acc[mi][ni], af[mi], bf[ni]);
        }
    }

    // Epilogue: y = (acc * x_scale + bias) * gate, straight from registers
#pragma unroll
    for (int mi = 0; mi < 2; mi++) {
        const int r = m0 + wm * 32 + mi * 16 + (lane >> 2);
        const float xs0 = __ldg(xscale + r);
        const float xs1 = __ldg(xscale + r + 8);
        const float* g0 = gate + (size_t)r * N_DIM;
        const float* g1 = g0 + (size_t)8 * N_DIM;
        float* o0 = out + (size_t)r * N_DIM;
        float* o1 = o0 + (size_t)8 * N_DIM;
#pragma unroll
        for (int ni = 0; ni < 4; ni++) {
            const int cc = n0 + wn * 32 + ni * 8 + (lane & 3) * 2;
            float2 bb = *reinterpret_cast<const float2*>(bias + cc);
            float2 ga = *reinterpret_cast<const float2*>(g0 + cc);
            float2 gb = *reinterpret_cast<const float2*>(g1 + cc);
            float2 v0, v1;
            v0.x = (acc[mi][ni][0] * xs0 + bb.x) * ga.x;
            v0.y = (acc[mi][ni][1] * xs0 + bb.y) * ga.y;
            v1.x = (acc[mi][ni][2] * xs1 + bb.x) * gb.x;
            v1.y = (acc[mi][ni][3] * xs1 + bb.y) * gb.y;
            *reinterpret_cast<float2*>(o0 + cc) = v0;
            *reinterpret_cast<float2*>(o1 + cc) = v1;
        }
    }
}

extern "C" void kernel_launch(void* const* d_in, const int* in_sizes, int n_in,
                              void* d_out, int out_size) {
    (void)in_sizes; (void)n_in; (void)out_size;
    const float* x      = (const float*)d_in[0];
    const float* xscale = (const float*)d_in[1];
    const int*   w4     = (const int*)d_in[2];
    const float* wsc    = (const float*)d_in[3];
    const float* gate   = (const float*)d_in[4];
    const float* bias   = (const float*)d_in[5];
    float* out = (float*)d_out;

    prep_kernel<<<XBLOCKS + WBLOCKS, 256>>>(x, w4, wsc);

    cudaFuncSetAttribute(gemm_kernel,
                         cudaFuncAttributeMaxDynamicSharedMemorySize, SMEM_TOTAL);
    gemm_kernel<<<MTILES * NTILES, THREADS, SMEM_TOTAL>>>(xscale, gate, bias, out);
}

// round 10
// speedup vs baseline: 1.1627x; 1.0526x over previous
#include <cuda_runtime.h>
#include <cuda_fp16.h>
#include <cstdint>

// Problem constants
#define M_DIM 8192
#define K_DIM 4096
#define N_DIM 14336
#define GSZ   128

// GEMM tiling: CTA 256x128, warp 64x32, 16 warps
#define MT 256
#define NT 128
#define KC 64                       // K per pipeline chunk
#define CHUNKS (K_DIM / KC)         // 64
#define STAGES 4
#define MTILES (M_DIM / MT)         // 32
#define NTILES (N_DIM / NT)         // 112
#define THREADS 512

#define A_STAGE (MT * KC * 2)       // 32 KB
#define B_STAGE (NT * KC * 2)       // 16 KB
#define STAGE_BYTES (A_STAGE + B_STAGE)     // 48 KB
#define SMEM_TOTAL (STAGES * STAGE_BYTES)   // 192 KB

// Fused prepass geometry
#define XV4     ((size_t)M_DIM * K_DIM / 4)   // float4 items
#define XBLOCKS ((int)(XV4 / 256))            // 32768
#define WWORDS  ((size_t)N_DIM * K_DIM / 8)   // packed int32 items
#define WBLOCKS ((int)(WWORDS / 256))         // 28672

// Pre-converted operands (device-global scratch; allocation-free)
__device__ __half g_xh[(size_t)M_DIM * K_DIM];   // 64 MB: x as fp16
__device__ __half g_wh[(size_t)N_DIM * K_DIM];   // 112 MB: dequantized W as fp16

__device__ __forceinline__ uint32_t s2u(const void* p) {
    uint32_t a;
    asm("{ .reg .u64 t; cvta.to.shared.u64 t, %1; cvt.u32.u64 %0, t; }" : "=r"(a) : "l"(p));
    return a;
}

__device__ __forceinline__ void cpa16(uint32_t dst, const void* src) {
    asm volatile("cp.async.cg.shared.global [%0], [%1], 16;" :: "r"(dst), "l"(src) : "memory");
}

// ---------------- Fused prepass: x fp32->fp16 AND int4 W -> fp16 ----------------
__global__ void prep_kernel(const float* __restrict__ x,
                            const int* __restrict__ w4,
                            const float* __restrict__ wsc) {
    if (blockIdx.x < XBLOCKS) {
        size_t i = (size_t)blockIdx.x * 256 + threadIdx.x;   // one float4
        float4 v = reinterpret_cast<const float4*>(x)[i];
        __half2 h0 = __floats2half2_rn(v.x, v.y);
        __half2 h1 = __floats2half2_rn(v.z, v.w);
        uint2 u;
        u.x = *reinterpret_cast<uint32_t*>(&h0);
        u.y = *reinterpret_cast<uint32_t*>(&h1);
        reinterpret_cast<uint2*>(g_xh)[i] = u;
    } else {
        size_t i = (size_t)(blockIdx.x - XBLOCKS) * 256 + threadIdx.x;  // one packed word
        int n  = (int)(i >> 9);           // K/8 = 512 words per row
        int kw = (int)(i & 511);
        uint32_t w = (uint32_t)w4[i];
        float s = __ldg(wsc + (size_t)n * (K_DIM / GSZ) + (kw >> 4));
        __half2 h[4];
#pragma unroll
        for (int p = 0; p < 4; p++) {
            int v0 = ((int)(w << (28 - 8 * p))) >> 28;        // nibble 2p
            int v1 = ((int)(w << (24 - 8 * p))) >> 28;        // nibble 2p+1
            h[p] = __floats2half2_rn((float)v0 * s, (float)v1 * s);
        }
        uint4 u;
        u.x = *reinterpret_cast<uint32_t*>(&h[0]);
        u.y = *reinterpret_cast<uint32_t*>(&h[1]);
        u.z = *reinterpret_cast<uint32_t*>(&h[2]);
        u.w = *reinterpret_cast<uint32_t*>(&h[3]);
        reinterpret_cast<uint4*>(g_wh)[i] = u;
    }
}

// ---------------- GEMM mainloop helpers ----------------
__device__ __forceinline__ void load_stage(uint32_t sstage, const __half* __restrict__ Ag,
                                           const __half* __restrict__ Bg, int k0, int tid) {
    // A: 256 rows x 8 chunks of 16B, XOR-swizzled within the 128B row
#pragma unroll
    for (int i = 0; i < 4; i++) {
        int ch = tid + i * 512;
        int r = ch >> 3, cc = ch & 7;
        cpa16(sstage + (uint32_t)((r << 7) + ((cc ^ (r & 7)) << 4)),
              Ag + (size_t)r * K_DIM + k0 + cc * 8);
    }
    // B: 128 rows x 8 chunks of 16B
#pragma unroll
    for (int i = 0; i < 2; i++) {
        int ch = tid + i * 512;
        int r = ch >> 3, cc = ch & 7;
        cpa16(sstage + A_STAGE + (uint32_t)((r << 7) + ((cc ^ (r & 7)) << 4)),
              Bg + (size_t)r * K_DIM + k0 + cc * 8);
    }
}

#define LDSM4(r0, r1, r2, r3, addr)                                         \
    asm volatile("ldmatrix.sync.aligned.m8n8.x4.shared.b16 {%0,%1,%2,%3}, [%4];" \
                 : "=r"(r0), "=r"(r1), "=r"(r2), "=r"(r3) : "r"(addr))

#define MMA16816(d, a, b)                                                   \
    asm volatile("mma.sync.aligned.m16n8k16.row.col.f32.f16.f16.f32 "       \
                 "{%0,%1,%2,%3}, {%4,%5,%6,%7}, {%8,%9}, {%0,%1,%2,%3};"    \
                 : "+f"(d[0]), "+f"(d[1]), "+f"(d[2]), "+f"(d[3])           \
                 : "r"(a[0]), "r"(a[1]), "r"(a[2]), "r"(a[3]),              \
                   "r"(b[0]), "r"(b[1]))

__global__ void __launch_bounds__(THREADS, 1)
gemm_kernel(const float* __restrict__ xscale, const float* __restrict__ gate,
            const float* __restrict__ bias, float* __restrict__ out)
{
    extern __shared__ char smem[];
    const uint32_t sbase = s2u(smem);
    const int tid = threadIdx.x;

    // Band rasterization: 4 M-tiles per panel for L2 reuse within a wave
    int pid = blockIdx.x;
    int panel = pid / (4 * NTILES);
    int rem = pid - panel * 4 * NTILES;
    int nt = rem >> 2;
    int mt = (panel << 2) + (rem & 3);
    const int m0 = mt * MT, n0 = nt * NT;

    const __half* Ag = g_xh + (size_t)m0 * K_DIM;
    const __half* Bg = g_wh + (size_t)n0 * K_DIM;

    // Prologue: fill STAGES-1 pipeline stages
#pragma unroll
    for (int c = 0; c < STAGES - 1; c++) {
        load_stage(sbase + (uint32_t)c * STAGE_BYTES, Ag, Bg, c * KC, tid);
        asm volatile("cp.async.commit_group;" ::: "memory");
    }

    const int lane = tid & 31, warp = tid >> 5;
    const int wm = warp & 3, wn = warp >> 2;           // warp grid 4(M) x 4(N)
    const int rl = lane & 15;                          // ldmatrix row-within-16
    const int cl = lane >> 4;                          // ldmatrix chunk select
    const int sw = lane & 7;                           // swizzle xor
    const uint32_t aoff = (uint32_t)((wm * 64 + rl) << 7);
    const uint32_t boff = (uint32_t)(A_STAGE + ((wn * 32 + rl) << 7));

    float acc[4][4][4];
#pragma unroll
    for (int mi = 0; mi < 4; mi++)
#pragma unroll
        for (int ni = 0; ni < 4; ni++)
#pragma unroll
            for (int j = 0; j < 4; j++) acc[mi][ni][j] = 0.0f;

#pragma unroll 1
    for (int c = 0; c < CHUNKS; c++) {
        asm volatile("cp.async.wait_group %0;" :: "n"(STAGES - 2) : "memory");
        __syncthreads();
        const int cn = c + STAGES - 1;
        if (cn < CHUNKS)
            load_stage(sbase + (uint32_t)(cn % STAGES) * STAGE_BYTES, Ag, Bg, cn * KC, tid);
        asm volatile("cp.async.commit_group;" ::: "memory");

        const uint32_t sa = sbase + (uint32_t)(c % STAGES) * STAGE_BYTES;
#pragma unroll
        for (int ks = 0; ks < 4; ks++) {
            const uint32_t coff = (uint32_t)((((ks << 1) + cl) ^ sw) << 4);
            uint32_t af[4][4], bf[4][2];
#pragma unroll
            for (int mi = 0; mi < 4; mi++)
                LDSM4(af[mi][0], af[mi][1], af[mi][2], af[mi][3],
                      sa + aoff + (uint32_t)(mi * 2048) + coff);
#pragma unroll
            for (int p = 0; p < 2; p++) {
                uint32_t r0, r1, r2, r3;
                LDSM4(r0, r1, r2, r3, sa + boff + (uint32_t)(p * 2048) + coff);
                bf[2 * p][0] = r0; bf[2 * p][1] = r2;
                bf[2 * p + 1][0] = r1; bf[2 * p + 1][1] = r3;
            }
#pragma unroll
            for (int mi = 0; mi < 4; mi++)
#pragma unroll
                for (int ni = 0; ni < 4; ni++)
                    MMA16816(acc[mi][ni], af[mi], bf[ni]);
        }
    }

    // Epilogue: y = (acc * x_scale + bias) * gate, straight from registers
#pragma unroll
    for (int mi = 0; mi < 4; mi++) {
        const int r = m0 + wm * 64 + mi * 16 + (lane >> 2);
        const float xs0 = __ldg(xscale + r);
        const float xs1 = __ldg(xscale + r + 8);
        const float* g0 = gate + (size_t)r * N_DIM;
        const float* g1 = g0 + (size_t)8 * N_DIM;
        float* o0 = out + (size_t)r * N_DIM;
        float* o1 = o0 + (size_t)8 * N_DIM;
#pragma unroll
        for (int ni = 0; ni < 4; ni++) {
            const int cc = n0 + wn * 32 + ni * 8 + (lane & 3) * 2;
            float2 bb = *reinterpret_cast<const float2*>(bias + cc);
            float2 ga = *reinterpret_cast<const float2*>(g0 + cc);
            float2 gb = *reinterpret_cast<const float2*>(g1 + cc);
            float2 v0, v1;
            v0.x = (acc[mi][ni][0] * xs0 + bb.x) * ga.x;
            v0.y = (acc[mi][ni][1] * xs0 + bb.y) * ga.y;
            v1.x = (acc[mi][ni][2] * xs1 + bb.x) * gb.x;
            v1.y = (acc[mi][ni][3] * xs1 + bb.y) * gb.y;
            *reinterpret_cast<float2*>(o0 + cc) = v0;
            *reinterpret_cast<float2*>(o1 + cc) = v1;
        }
    }
}

extern "C" void kernel_launch(void* const* d_in, const int* in_sizes, int n_in,
                              void* d_out, int out_size) {
    (void)in_sizes; (void)n_in; (void)out_size;
    const float* x      = (const float*)d_in[0];
    const float* xscale = (const float*)d_in[1];
    const int*   w4     = (const int*)d_in[2];
    const float* wsc    = (const float*)d_in[3];
    const float* gate   = (const float*)d_in[4];
    const float* bias   = (const float*)d_in[5];
    float* out = (float*)d_out;

    prep_kernel<<<XBLOCKS + WBLOCKS, 256>>>(x, w4, wsc);

    cudaFuncSetAttribute(gemm_kernel,
                         cudaFuncAttributeMaxDynamicSharedMemorySize, SMEM_TOTAL);
    gemm_kernel<<<MTILES * NTILES, THREADS, SMEM_TOTAL>>>(xscale, gate, bias, out);
}

// round 14
// speedup vs baseline: 1.2498x; 1.0749x over previous
#include <cuda_runtime.h>
#include <cuda_fp16.h>
#include <cstdint>

// Problem constants
#define M_DIM 8192
#define K_DIM 4096
#define N_DIM 14336
#define GSZ   128

// GEMM tiling: CTA 128x128, 8 warps (4M x 2N), warp tile 32x64, 2 CTAs/SM
#define MT 128
#define NT 128
#define KC 64                       // K per pipeline chunk
#define CHUNKS (K_DIM / KC)         // 64
#define STAGES 3
#define MTILES (M_DIM / MT)         // 64
#define NTILES (N_DIM / NT)         // 112
#define THREADS 256

#define A_STAGE (MT * KC * 2)       // 16 KB
#define B_STAGE (NT * KC * 2)       // 16 KB
#define STAGE_BYTES (A_STAGE + B_STAGE)     // 32 KB
#define SMEM_TOTAL (STAGES * STAGE_BYTES)   // 96 KB -> 2 CTAs/SM

// Fused prepass geometry
#define XV4     ((size_t)M_DIM * K_DIM / 4)   // float4 items
#define XBLOCKS ((int)(XV4 / 256))            // 32768
#define WWORDS  ((size_t)N_DIM * K_DIM / 8)   // packed int32 items
#define WBLOCKS ((int)(WWORDS / 256))         // 28672

// Pre-converted operands (device-global scratch; allocation-free)
__device__ __half g_xh[(size_t)M_DIM * K_DIM];   // 64 MB: x as fp16
__device__ __half g_wh[(size_t)N_DIM * K_DIM];   // 112 MB: dequantized W as fp16

__device__ __forceinline__ uint32_t s2u(const void* p) {
    uint32_t a;
    asm("{ .reg .u64 t; cvta.to.shared.u64 t, %1; cvt.u32.u64 %0, t; }" : "=r"(a) : "l"(p));
    return a;
}

__device__ __forceinline__ void cpa16(uint32_t dst, const void* src) {
    asm volatile("cp.async.cg.shared.global [%0], [%1], 16;" :: "r"(dst), "l"(src) : "memory");
}

// ---------------- Fused prepass: x fp32->fp16 AND int4 W -> fp16 ----------------
__global__ void prep_kernel(const float* __restrict__ x,
                            const int* __restrict__ w4,
                            const float* __restrict__ wsc) {
    if (blockIdx.x < XBLOCKS) {
        size_t i = (size_t)blockIdx.x * 256 + threadIdx.x;   // one float4
        float4 v = reinterpret_cast<const float4*>(x)[i];
        __half2 h0 = __floats2half2_rn(v.x, v.y);
        __half2 h1 = __floats2half2_rn(v.z, v.w);
        uint2 u;
        u.x = *reinterpret_cast<uint32_t*>(&h0);
        u.y = *reinterpret_cast<uint32_t*>(&h1);
        reinterpret_cast<uint2*>(g_xh)[i] = u;
    } else {
        size_t i = (size_t)(blockIdx.x - XBLOCKS) * 256 + threadIdx.x;  // one packed word
        int n  = (int)(i >> 9);           // K/8 = 512 words per row
        int kw = (int)(i & 511);
        uint32_t w = (uint32_t)w4[i];
        float s = __ldg(wsc + (size_t)n * (K_DIM / GSZ) + (kw >> 4));
        __half2 h[4];
#pragma unroll
        for (int p = 0; p < 4; p++) {
            int v0 = ((int)(w << (28 - 8 * p))) >> 28;        // nibble 2p
            int v1 = ((int)(w << (24 - 8 * p))) >> 28;        // nibble 2p+1
            h[p] = __floats2half2_rn((float)v0 * s, (float)v1 * s);
        }
        uint4 u;
        u.x = *reinterpret_cast<uint32_t*>(&h[0]);
        u.y = *reinterpret_cast<uint32_t*>(&h[1]);
        u.z = *reinterpret_cast<uint32_t*>(&h[2]);
        u.w = *reinterpret_cast<uint32_t*>(&h[3]);
        reinterpret_cast<uint4*>(g_wh)[i] = u;
    }
}

// ---------------- GEMM mainloop helpers ----------------
__device__ __forceinline__ void load_stage(uint32_t sstage, const __half* __restrict__ Ag,
                                           const __half* __restrict__ Bg, int k0, int tid) {
    // A: 128 rows x 8 chunks of 16B, XOR-swizzled within the 128B row
#pragma unroll
    for (int i = 0; i < 4; i++) {
        int ch = tid + i * 256;
        int r = ch >> 3, cc = ch & 7;
        cpa16(sstage + (uint32_t)((r << 7) + ((cc ^ (r & 7)) << 4)),
              Ag + (size_t)r * K_DIM + k0 + cc * 8);
    }
    // B: 128 rows x 8 chunks of 16B
#pragma unroll
    for (int i = 0; i < 4; i++) {
        int ch = tid + i * 256;
        int r = ch >> 3, cc = ch & 7;
        cpa16(sstage + A_STAGE + (uint32_t)((r << 7) + ((cc ^ (r & 7)) << 4)),
              Bg + (size_t)r * K_DIM + k0 + cc * 8);
    }
}

#define LDSM4(r0, r1, r2, r3, addr)                                         \
    asm volatile("ldmatrix.sync.aligned.m8n8.x4.shared.b16 {%0,%1,%2,%3}, [%4];" \
                 : "=r"(r0), "=r"(r1), "=r"(r2), "=r"(r3) : "r"(addr))

#define MMA16816(d, a, b)                                                   \
    asm volatile("mma.sync.aligned.m16n8k16.row.col.f32.f16.f16.f32 "       \
                 "{%0,%1,%2,%3}, {%4,%5,%6,%7}, {%8,%9}, {%0,%1,%2,%3};"    \
                 : "+f"(d[0]), "+f"(d[1]), "+f"(d[2]), "+f"(d[3])           \
                 : "r"(a[0]), "r"(a[1]), "r"(a[2]), "r"(a[3]),              \
                   "r"(b[0]), "r"(b[1]))

__global__ void __launch_bounds__(THREADS, 2)
gemm_kernel(const float* __restrict__ xscale, const float* __restrict__ gate,
            const float* __restrict__ bias, float* __restrict__ out)
{
    extern __shared__ char smem[];
    const uint32_t sbase = s2u(smem);
    const int tid = threadIdx.x;

    // Band rasterization: 8 M-tiles per panel for L2 reuse within a wave
    int pid = blockIdx.x;
    int panel = pid / (8 * NTILES);
    int rem = pid - panel * 8 * NTILES;
    int nt = rem >> 3;
    int mt = (panel << 3) + (rem & 7);
    const int m0 = mt * MT, n0 = nt * NT;

    const __half* Ag = g_xh + (size_t)m0 * K_DIM;
    const __half* Bg = g_wh + (size_t)n0 * K_DIM;

    // Prologue: fill STAGES-1 pipeline stages
#pragma unroll
    for (int c = 0; c < STAGES - 1; c++) {
        load_stage(sbase + (uint32_t)c * STAGE_BYTES, Ag, Bg, c * KC, tid);
        asm volatile("cp.async.commit_group;" ::: "memory");
    }

    const int lane = tid & 31, warp = tid >> 5;
    const int wm = warp & 3, wn = warp >> 2;           // warp grid 4(M) x 2(N)
    const int rl = lane & 15;                          // ldmatrix row-within-16
    const int cl = lane >> 4;                          // ldmatrix chunk select
    const int sw = lane & 7;                           // swizzle xor
    const uint32_t aoff = (uint32_t)((wm * 32 + rl) << 7);
    const uint32_t boff = (uint32_t)(A_STAGE + ((wn * 64 + rl) << 7));

    float acc[2][8][4];
#pragma unroll
    for (int mi = 0; mi < 2; mi++)
#pragma unroll
        for (int ni = 0; ni < 8; ni++)
#pragma unroll
            for (int j = 0; j < 4; j++) acc[mi][ni][j] = 0.0f;

#pragma unroll 1
    for (int c = 0; c < CHUNKS; c++) {
        asm volatile("cp.async.wait_group %0;" :: "n"(STAGES - 2) : "memory");
        __syncthreads();
        const int cn = c + STAGES - 1;
        if (cn < CHUNKS)
            load_stage(sbase + (uint32_t)(cn % STAGES) * STAGE_BYTES, Ag, Bg, cn * KC, tid);
        asm volatile("cp.async.commit_group;" ::: "memory");

        const uint32_t sa = sbase + (uint32_t)(c % STAGES) * STAGE_BYTES;
#pragma unroll
        for (int ks = 0; ks < 4; ks++) {
            const uint32_t coff = (uint32_t)((((ks << 1) + cl) ^ sw) << 4);
            uint32_t af[2][4], bf[8][2];
#pragma unroll
            for (int mi = 0; mi < 2; mi++)
                LDSM4(af[mi][0], af[mi][1], af[mi][2], af[mi][3],
                      sa + aoff + (uint32_t)(mi * 2048) + coff);
#pragma unroll
            for (int p = 0; p < 4; p++) {
                uint32_t r0, r1, r2, r3;
                LDSM4(r0, r1, r2, r3, sa + boff + (uint32_t)(p * 2048) + coff);
                bf[2 * p][0] = r0; bf[2 * p][1] = r2;
                bf[2 * p + 1][0] = r1; bf[2 * p + 1][1] = r3;
            }
#pragma unroll
            for (int mi = 0; mi < 2; mi++)
#pragma unroll
                for (int ni = 0; ni < 8; ni++)
                    MMA16816(acc[mi][ni], af[mi], bf[ni]);
        }
    }

    // Epilogue: y = (acc * x_scale + bias) * gate, straight from registers
#pragma unroll
    for (int mi = 0; mi < 2; mi++) {
        const int r = m0 + wm * 32 + mi * 16 + (lane >> 2);
        const float xs0 = __ldg(xscale + r);
        const float xs1 = __ldg(xscale + r + 8);
        const float* g0 = gate + (size_t)r * N_DIM;
        const float* g1 = g0 + (size_t)8 * N_DIM;
        float* o0 = out + (size_t)r * N_DIM;
        float* o1 = o0 + (size_t)8 * N_DIM;
#pragma unroll
        for (int ni = 0; ni < 8; ni++) {
            const int cc = n0 + wn * 64 + ni * 8 + (lane & 3) * 2;
            float2 bb = *reinterpret_cast<const float2*>(bias + cc);
            float2 ga = *reinterpret_cast<const float2*>(g0 + cc);
            float2 gb = *reinterpret_cast<const float2*>(g1 + cc);
            float2 v0, v1;
            v0.x = (acc[mi][ni][0] * xs0 + bb.x) * ga.x;
            v0.y = (acc[mi][ni][1] * xs0 + bb.y) * ga.y;
            v1.x = (acc[mi][ni][2] * xs1 + bb.x) * gb.x;
            v1.y = (acc[mi][ni][3] * xs1 + bb.y) * gb.y;
            *reinterpret_cast<float2*>(o0 + cc) = v0;
            *reinterpret_cast<float2*>(o1 + cc) = v1;
        }
    }
}

extern "C" void kernel_launch(void* const* d_in, const int* in_sizes, int n_in,
                              void* d_out, int out_size) {
    (void)in_sizes; (void)n_in; (void)out_size;
    const float* x      = (const float*)d_in[0];
    const float* xscale = (const float*)d_in[1];
    const int*   w4     = (const int*)d_in[2];
    const float* wsc    = (const float*)d_in[3];
    const float* gate   = (const float*)d_in[4];
    const float* bias   = (const float*)d_in[5];
    float* out = (float*)d_out;

    prep_kernel<<<XBLOCKS + WBLOCKS, 256>>>(x, w4, wsc);

    cudaFuncSetAttribute(gemm_kernel,
                         cudaFuncAttributeMaxDynamicSharedMemorySize, SMEM_TOTAL);
    gemm_kernel<<<MTILES * NTILES, THREADS, SMEM_TOTAL>>>(xscale, gate, bias, out);
}